// round 16
// baseline (speedup 1.0000x reference)
#include <cuda_runtime.h>
#include <cuda_fp16.h>
#include <math.h>

#define N_NODES 100000
#define N_EDGES 3200000
#define FIN 16
#define H 64
#define CAP 128                 // fixed CSR row capacity (mean deg 32, P(>128)~e-32)
#define NGRP 25000              // 4-node groups (N_NODES / 4 exactly)

// ---------------- scratch (static device globals) ----------------
__device__ int     g_deg  [N_NODES];
__device__ int     g_csr  [N_NODES * CAP];  // 51.2MB fixed-stride CSR
__device__ float   g_dis  [N_NODES];
__device__ float4  g_a16  [N_NODES * 4];    // layer-1 aggregate * dis (16 f32/node)
__device__ __half2 g_sx16h[N_NODES * 8];    // x * dis     (16 fp16/node, 32B rows)
__device__ __half2 g_sx64h[N_NODES * 32];   // (h@W2)*dis  (64 fp16/node, 128B rows)

// ---------------- packed f32x2 helpers (Blackwell; PTX-only) ----------------
__device__ __forceinline__ unsigned long long pk2(float x, float y) {
    unsigned long long r;
    asm("mov.b64 %0, {%1, %2};" : "=l"(r) : "f"(x), "f"(y));
    return r;
}
__device__ __forceinline__ float2 upk2(unsigned long long v) {
    float2 f;
    asm("mov.b64 {%0, %1}, %2;" : "=f"(f.x), "=f"(f.y) : "l"(v));
    return f;
}
__device__ __forceinline__ void fmax2(unsigned long long& acc, unsigned long long a,
                                      unsigned long long b) {
    asm("fma.rn.f32x2 %0, %1, %2, %3;" : "=l"(acc) : "l"(a), "l"(b), "l"(acc));
}

// --------- per-warp int64/int32 probe: first 256B of edge buffer (L2-broadcast) ---------
__device__ __forceinline__ int detect64(const void* ei) {
    int lane = threadIdx.x & 31;
    int w = ((const int*)ei)[2 * lane + 1];           // odd words: 0 iff int64 (<2^31)
    unsigned m = __ballot_sync(0xffffffffu, w == 0);
    return __popc(m) >= 24;
}

// ------- scatter + degree in ONE pass: 8 edges/thread, fixed-stride CSR -------
__global__ void __launch_bounds__(256) k_scatter(const void* __restrict__ ei) {
    int is64 = detect64(ei);
    int t = blockIdx.x * blockDim.x + threadIdx.x;    // N_EDGES/8 threads
    if (t >= N_EDGES / 8) return;
    int r[8], c[8];
    if (is64) {
        const longlong2* rp = (const longlong2*)ei;
        const longlong2* cp = (const longlong2*)((const long long*)ei + N_EDGES);
        #pragma unroll
        for (int q = 0; q < 4; q++) {
            longlong2 rv = rp[4 * t + q], cv = cp[4 * t + q];
            r[2*q] = (int)rv.x; r[2*q+1] = (int)rv.y;
            c[2*q] = (int)cv.x; c[2*q+1] = (int)cv.y;
        }
    } else {
        const int4* rp = (const int4*)ei;
        const int4* cp = (const int4*)((const int*)ei + N_EDGES);
        #pragma unroll
        for (int q = 0; q < 2; q++) {
            int4 rv = rp[2 * t + q], cv = cp[2 * t + q];
            r[4*q] = rv.x; r[4*q+1] = rv.y; r[4*q+2] = rv.z; r[4*q+3] = rv.w;
            c[4*q] = cv.x; c[4*q+1] = cv.y; c[4*q+2] = cv.z; c[4*q+3] = cv.w;
        }
    }
    int p[8];
    #pragma unroll
    for (int q = 0; q < 8; q++) {
        p[q] = -1;
        if ((unsigned)c[q] < N_NODES && (unsigned)r[q] < N_NODES)
            p[q] = atomicAdd(&g_deg[c[q]], 1);
    }
    #pragma unroll
    for (int q = 0; q < 8; q++)
        if (p[q] >= 0 && p[q] < CAP) g_csr[c[q] * CAP + p[q]] = r[q];
}

// ---------------- prep: dis = rsqrt(deg+1); sx16 = fp16(x * dis) ----------------
__global__ void __launch_bounds__(256) k_prep(const float* __restrict__ x) {
    int t = blockIdx.x * blockDim.x + threadIdx.x;    // N*4 threads
    if (t >= N_NODES * 4) return;
    int n = t >> 2;
    float d = rsqrtf((float)(g_deg[n] + 1));          // +1 self-loop
    if ((t & 3) == 0) g_dis[n] = d;
    float4 vx = ((const float4*)x)[t];
    __half2 h0 = __floats2half2_rn(vx.x * d, vx.y * d);
    __half2 h1 = __floats2half2_rn(vx.z * d, vx.w * d);
    uint2 u;
    u.x = *(unsigned*)&h0; u.y = *(unsigned*)&h1;
    ((uint2*)g_sx16h)[t] = u;
}

__device__ __forceinline__ void acc_h4(float4& a, uint2 u) {
    float2 p = __half22float2(*(__half2*)&u.x), q = __half22float2(*(__half2*)&u.y);
    a.x += p.x; a.y += p.y; a.z += q.x; a.w += q.y;
}

// ---------------- agg1: pure 16-wide fp16 gather, no smem ----------------
__global__ void __launch_bounds__(256) k_agg1() {
    int tid = blockIdx.x * blockDim.x + threadIdx.x;   // 4 threads per node
    int n = tid >> 2, j = tid & 3;
    if (n >= N_NODES) return;
    const uint2* sx = (const uint2*)g_sx16h;           // 4 uint2 per 32B row
    const int* row = &g_csr[n * CAP];

    float4 acc = make_float4(0.f, 0.f, 0.f, 0.f);
    acc_h4(acc, sx[n * 4 + j]);                        // self-loop
    int end = g_deg[n]; if (end > CAP) end = CAP;
    int i = 0;
    for (; i + 8 <= end; i += 8) {
        uint2 u0 = sx[row[i+0]*4+j], u1 = sx[row[i+1]*4+j];
        uint2 u2 = sx[row[i+2]*4+j], u3 = sx[row[i+3]*4+j];
        uint2 u4 = sx[row[i+4]*4+j], u5 = sx[row[i+5]*4+j];
        uint2 u6 = sx[row[i+6]*4+j], u7 = sx[row[i+7]*4+j];
        acc_h4(acc, u0); acc_h4(acc, u1); acc_h4(acc, u2); acc_h4(acc, u3);
        acc_h4(acc, u4); acc_h4(acc, u5); acc_h4(acc, u6); acc_h4(acc, u7);
    }
    for (; i < end; i++) acc_h4(acc, sx[row[i]*4+j]);
    float d = g_dis[n];
    acc.x *= d; acc.y *= d; acc.z *= d; acc.w *= d;
    g_a16[n * 4 + j] = acc;
}

// ---- gemm: h = relu(a16@W1+b1); sx64 = (h@W2)*dis -> fp16 ----
// 8 lanes per 4-node group, packed f32x2 FMA (2 fp32 ops/instr), h in regs + shfl.
#define ASTR 20
__global__ void __launch_bounds__(256) k_gemm(const float* __restrict__ W1,
                                              const float* __restrict__ b1,
                                              const float* __restrict__ W2) {
    __shared__ __align__(16) float sW1[FIN * H];      // 4KB
    __shared__ __align__(16) float sW2[H * H];        // 16KB
    __shared__ __align__(16) float sb1[H];
    __shared__ __align__(16) float sA[128 * ASTR];    // 10KB: 128 nodes' aggregates
    __shared__ float sdis[128];
    int tid = threadIdx.x;
    int lg = tid >> 3;                 // local group 0..31
    int j  = tid & 7;                  // lane-in-group
    int lane = tid & 31;
    int base_lane = lane & 24;         // first lane of this 8-lane group
    int grp = blockIdx.x * 32 + lg;    // global group (4 nodes each)
    int n0 = grp * 4;

    // vectorized preloads
    for (int k = tid; k < FIN * H / 4; k += 256) ((float4*)sW1)[k] = ((const float4*)W1)[k];
    for (int k = tid; k < H * H / 4; k += 256)   ((float4*)sW2)[k] = ((const float4*)W2)[k];
    if (tid < H) sb1[tid] = b1[tid];
    {
        int nb = blockIdx.x * 128;
        #pragma unroll
        for (int w = 0; w < 2; w++) {
            int idx = w * 256 + tid;           // 0..511
            int nn = idx >> 2, q = idx & 3;
            float4 v = make_float4(0.f, 0.f, 0.f, 0.f);
            if (nb + nn < N_NODES) v = g_a16[(nb + nn) * 4 + q];
            *(float4*)&sA[nn * ASTR + q * 4] = v;
        }
        if (tid < 128) sdis[tid] = (nb + tid < N_NODES) ? g_dis[nb + tid] : 0.0f;
    }
    __syncthreads();

    // phase 2: h[m][8] = relu(a @ W1 + b1); f32x2 packed accumulators (4 pairs per m)
    float h[32];
    {
        unsigned long long acc2[16];
        float4 bq0 = *(const float4*)&sb1[j * 4];
        float4 bq1 = *(const float4*)&sb1[32 + j * 4];
        unsigned long long b0 = pk2(bq0.x, bq0.y), b1p = pk2(bq0.z, bq0.w);
        unsigned long long b2 = pk2(bq1.x, bq1.y), b3p = pk2(bq1.z, bq1.w);
        #pragma unroll
        for (int m = 0; m < 4; m++) {
            acc2[m*4+0] = b0; acc2[m*4+1] = b1p; acc2[m*4+2] = b2; acc2[m*4+3] = b3p;
        }
        #pragma unroll 4
        for (int k = 0; k < FIN; k++) {
            ulonglong2 wa = *(const ulonglong2*)&sW1[k * H + j * 4];
            ulonglong2 wb = *(const ulonglong2*)&sW1[k * H + 32 + j * 4];
            #pragma unroll
            for (int m = 0; m < 4; m++) {
                float av = sA[(lg * 4 + m) * ASTR + k];
                unsigned long long ap = pk2(av, av);
                fmax2(acc2[m*4+0], ap, wa.x);
                fmax2(acc2[m*4+1], ap, wa.y);
                fmax2(acc2[m*4+2], ap, wb.x);
                fmax2(acc2[m*4+3], ap, wb.y);
            }
        }
        #pragma unroll
        for (int q = 0; q < 16; q++) {
            float2 f = upk2(acc2[q]);
            h[q*2+0] = fmaxf(f.x, 0.0f);
            h[q*2+1] = fmaxf(f.y, 0.0f);
        }
    }
    // h layout: h[m*8 + p] where pair index maps: outputs {4j..4j+3} = h[m*8+0..3],
    // outputs {32+4j..32+4j+3} = h[m*8+4..7] (same as R15 layout)

    // phase 3: packed f32x2 accumulators; one W2 ulonglong2 pair per k feeds 4 nodes
    unsigned long long acc3[16];
    #pragma unroll
    for (int q = 0; q < 16; q++) acc3[q] = 0ULL;
    #pragma unroll 4
    for (int k = 0; k < H; k++) {
        int owner = (k >> 2) & 7;                     // quad owner lane-in-group
        int hidx  = (k & 3) + ((k >> 5) << 2);        // register index at owner
        ulonglong2 wa = *(const ulonglong2*)&sW2[k * H + j * 4];
        ulonglong2 wb = *(const ulonglong2*)&sW2[k * H + 32 + j * 4];
        #pragma unroll
        for (int m = 0; m < 4; m++) {
            float hv = __shfl_sync(0xffffffffu, h[m*8 + hidx], base_lane + owner);
            unsigned long long hp = pk2(hv, hv);
            fmax2(acc3[m*4+0], hp, wa.x);
            fmax2(acc3[m*4+1], hp, wa.y);
            fmax2(acc3[m*4+2], hp, wb.x);
            fmax2(acc3[m*4+3], hp, wb.y);
        }
    }
    // scale + fp16 pack + store (guarded; all shfl/compute above is warp-uniform)
    if (grp < NGRP) {
        #pragma unroll
        for (int m = 0; m < 4; m++) {
            int n = n0 + m;
            float d = sdis[lg * 4 + m];
            float2 f0 = upk2(acc3[m*4+0]), f1 = upk2(acc3[m*4+1]);
            float2 f2 = upk2(acc3[m*4+2]), f3 = upk2(acc3[m*4+3]);
            __half2 p0 = __floats2half2_rn(f0.x*d, f0.y*d);
            __half2 p1 = __floats2half2_rn(f1.x*d, f1.y*d);
            __half2 p2 = __floats2half2_rn(f2.x*d, f2.y*d);
            __half2 p3 = __floats2half2_rn(f3.x*d, f3.y*d);
            uint2* row = (uint2*)&g_sx64h[n * 32];
            uint2 u0, u1;
            u0.x = *(unsigned*)&p0; u0.y = *(unsigned*)&p1;
            u1.x = *(unsigned*)&p2; u1.y = *(unsigned*)&p3;
            row[j]     = u0;
            row[8 + j] = u1;
        }
    }
}

// ---------------- agg2 (64-wide fp16 gather, unroll 8) + final scorer ----------------
__global__ void __launch_bounds__(128) k_agg2_fin(const float* __restrict__ b2,
                                                  const float* __restrict__ Wf,
                                                  const float* __restrict__ bf,
                                                  float* __restrict__ out) {
    int tid = blockIdx.x * blockDim.x + threadIdx.x;   // 16 threads per node
    int n = tid >> 4, j = tid & 15;
    if (n >= N_NODES) return;
    const uint2* sx = (const uint2*)g_sx64h;           // 16 uint2 per 128B row
    const int* row = &g_csr[n * CAP];

    float4 acc = make_float4(0.f, 0.f, 0.f, 0.f);
    acc_h4(acc, sx[n * 16 + j]);                       // self-loop
    int end = g_deg[n]; if (end > CAP) end = CAP;
    int i = 0;
    for (; i + 8 <= end; i += 8) {
        uint2 u0 = sx[row[i+0]*16+j], u1 = sx[row[i+1]*16+j];
        uint2 u2 = sx[row[i+2]*16+j], u3 = sx[row[i+3]*16+j];
        uint2 u4 = sx[row[i+4]*16+j], u5 = sx[row[i+5]*16+j];
        uint2 u6 = sx[row[i+6]*16+j], u7 = sx[row[i+7]*16+j];
        acc_h4(acc, u0); acc_h4(acc, u1); acc_h4(acc, u2); acc_h4(acc, u3);
        acc_h4(acc, u4); acc_h4(acc, u5); acc_h4(acc, u6); acc_h4(acc, u7);
    }
    for (; i < end; i++) acc_h4(acc, sx[row[i]*16+j]);

    float d = g_dis[n];
    float4 b = ((const float4*)b2)[j];
    float4 w = ((const float4*)Wf)[j];
    float s = fmaxf(fmaf(acc.x, d, b.x), 0.0f) * w.x
            + fmaxf(fmaf(acc.y, d, b.y), 0.0f) * w.y
            + fmaxf(fmaf(acc.z, d, b.z), 0.0f) * w.z
            + fmaxf(fmaf(acc.w, d, b.w), 0.0f) * w.w;
    #pragma unroll
    for (int off = 8; off > 0; off >>= 1) s += __shfl_down_sync(0xffffffffu, s, off, 16);
    if (j == 0) out[n] = 1.0f / (1.0f + expf(-(s + bf[0])));
}

// ---------------- launch ----------------
extern "C" void kernel_launch(void* const* d_in, const int* in_sizes, int n_in,
                              void* d_out, int out_size) {
    int iX = 0, iEi = 1, iW1 = 2, iW2 = 4, iBf = 7;
    int p64[3] = {3, 5, 6}; int n64 = 0;
    for (int i = 0; i < n_in; i++) {
        int s = in_sizes[i];
        if (s == 2 * N_EDGES)        iEi = i;
        else if (s == N_NODES * FIN) iX = i;
        else if (s == FIN * H)       iW1 = i;
        else if (s == H * H)         iW2 = i;
        else if (s == 1)             iBf = i;
        else if (s == H && n64 < 3)  p64[n64++] = i;
    }
    int iB1, iB2, iWf;
    if (n64 == 3 && p64[0] > iW2) { iWf = p64[0]; iB1 = p64[1]; iB2 = p64[2]; }
    else                          { iB1 = p64[0]; iB2 = p64[1]; iWf = p64[2]; }

    const float* x  = (const float*)d_in[iX];
    const void*  ei = d_in[iEi];
    const float* W1 = (const float*)d_in[iW1];
    const float* b1 = (const float*)d_in[iB1];
    const float* W2 = (const float*)d_in[iW2];
    const float* b2 = (const float*)d_in[iB2];
    const float* Wf = (const float*)d_in[iWf];
    const float* bf = (const float*)d_in[iBf];
    float* out = (float*)d_out;

    // zero degree via captured memset node (graph-legal, no alloc)
    void* p_deg = nullptr;
    cudaGetSymbolAddress(&p_deg, g_deg);
    cudaMemsetAsync(p_deg, 0, N_NODES * sizeof(int));

    k_scatter <<<(N_EDGES / 8 + 255) / 256, 256>>>(ei);
    k_prep    <<<(N_NODES * 4 + 255) / 256, 256>>>(x);
    k_agg1    <<<(N_NODES * 4 + 255) / 256, 256>>>();
    k_gemm    <<<(NGRP + 31) / 32, 256>>>(W1, b1, W2);
    k_agg2_fin<<<(N_NODES * 16 + 127) / 128, 128>>>(b2, Wf, bf, out);
}

// round 17
// speedup vs baseline: 1.0436x; 1.0436x over previous
#include <cuda_runtime.h>
#include <cuda_fp16.h>
#include <math.h>

#define N_NODES 100000
#define N_EDGES 3200000
#define FIN 16
#define H 64
#define CAP 128                 // fixed CSR row capacity (mean deg 32, P(>128)~e-32)
#define NGRP 25000              // 4-node groups (N_NODES / 4 exactly)

// ---------------- scratch (static device globals) ----------------
__device__ int     g_deg  [N_NODES];
__device__ int     g_csr  [N_NODES * CAP];  // 51.2MB fixed-stride CSR
__device__ float   g_dis  [N_NODES];
__device__ float4  g_a16  [N_NODES * 4];    // layer-1 aggregate * dis (16 f32/node)
__device__ __half2 g_sx16h[N_NODES * 8];    // x * dis     (16 fp16/node, 32B rows)
__device__ __half2 g_sx64h[N_NODES * 32];   // (h@W2)*dis  (64 fp16/node, 128B rows)

// ---------------- packed f32x2 helpers (Blackwell; PTX-only) ----------------
__device__ __forceinline__ unsigned long long pk2(float x, float y) {
    unsigned long long r;
    asm("mov.b64 %0, {%1, %2};" : "=l"(r) : "f"(x), "f"(y));
    return r;
}
__device__ __forceinline__ float2 upk2(unsigned long long v) {
    float2 f;
    asm("mov.b64 {%0, %1}, %2;" : "=f"(f.x), "=f"(f.y) : "l"(v));
    return f;
}
__device__ __forceinline__ void fmax2(unsigned long long& acc, unsigned long long a,
                                      unsigned long long b) {
    asm("fma.rn.f32x2 %0, %1, %2, %3;" : "=l"(acc) : "l"(a), "l"(b), "l"(acc));
}

// --------- per-warp int64/int32 probe: first 256B of edge buffer (L2-broadcast) ---------
__device__ __forceinline__ int detect64(const void* ei) {
    int lane = threadIdx.x & 31;
    int w = ((const int*)ei)[2 * lane + 1];           // odd words: 0 iff int64 (<2^31)
    unsigned m = __ballot_sync(0xffffffffu, w == 0);
    return __popc(m) >= 24;
}

// ------- scatter + degree in ONE pass: 8 edges/thread, fixed-stride CSR -------
__global__ void __launch_bounds__(256) k_scatter(const void* __restrict__ ei) {
    int is64 = detect64(ei);
    int t = blockIdx.x * blockDim.x + threadIdx.x;    // N_EDGES/8 threads
    if (t >= N_EDGES / 8) return;
    int r[8], c[8];
    if (is64) {
        const longlong2* rp = (const longlong2*)ei;
        const longlong2* cp = (const longlong2*)((const long long*)ei + N_EDGES);
        #pragma unroll
        for (int q = 0; q < 4; q++) {
            longlong2 rv = rp[4 * t + q], cv = cp[4 * t + q];
            r[2*q] = (int)rv.x; r[2*q+1] = (int)rv.y;
            c[2*q] = (int)cv.x; c[2*q+1] = (int)cv.y;
        }
    } else {
        const int4* rp = (const int4*)ei;
        const int4* cp = (const int4*)((const int*)ei + N_EDGES);
        #pragma unroll
        for (int q = 0; q < 2; q++) {
            int4 rv = rp[2 * t + q], cv = cp[2 * t + q];
            r[4*q] = rv.x; r[4*q+1] = rv.y; r[4*q+2] = rv.z; r[4*q+3] = rv.w;
            c[4*q] = cv.x; c[4*q+1] = cv.y; c[4*q+2] = cv.z; c[4*q+3] = cv.w;
        }
    }
    int p[8];
    #pragma unroll
    for (int q = 0; q < 8; q++) {
        p[q] = -1;
        if ((unsigned)c[q] < N_NODES && (unsigned)r[q] < N_NODES)
            p[q] = atomicAdd(&g_deg[c[q]], 1);
    }
    #pragma unroll
    for (int q = 0; q < 8; q++)
        if (p[q] >= 0 && p[q] < CAP) g_csr[c[q] * CAP + p[q]] = r[q];
}

// ---------------- prep: dis = rsqrt(deg+1); sx16 = fp16(x * dis) ----------------
__global__ void __launch_bounds__(256) k_prep(const float* __restrict__ x) {
    int t = blockIdx.x * blockDim.x + threadIdx.x;    // N*4 threads
    if (t >= N_NODES * 4) return;
    int n = t >> 2;
    float d = rsqrtf((float)(g_deg[n] + 1));          // +1 self-loop
    if ((t & 3) == 0) g_dis[n] = d;
    float4 vx = ((const float4*)x)[t];
    __half2 h0 = __floats2half2_rn(vx.x * d, vx.y * d);
    __half2 h1 = __floats2half2_rn(vx.z * d, vx.w * d);
    uint2 u;
    u.x = *(unsigned*)&h0; u.y = *(unsigned*)&h1;
    ((uint2*)g_sx16h)[t] = u;
}

__device__ __forceinline__ void acc_h4(float4& a, uint2 u) {
    float2 p = __half22float2(*(__half2*)&u.x), q = __half22float2(*(__half2*)&u.y);
    a.x += p.x; a.y += p.y; a.z += q.x; a.w += q.y;
}

// ---------------- agg1: pure 16-wide fp16 gather, no smem ----------------
__global__ void __launch_bounds__(256) k_agg1() {
    int tid = blockIdx.x * blockDim.x + threadIdx.x;   // 4 threads per node
    int n = tid >> 2, j = tid & 3;
    if (n >= N_NODES) return;
    const uint2* sx = (const uint2*)g_sx16h;           // 4 uint2 per 32B row
    const int* row = &g_csr[n * CAP];

    float4 acc = make_float4(0.f, 0.f, 0.f, 0.f);
    acc_h4(acc, sx[n * 4 + j]);                        // self-loop
    int end = g_deg[n]; if (end > CAP) end = CAP;
    int i = 0;
    for (; i + 8 <= end; i += 8) {
        uint2 u0 = sx[row[i+0]*4+j], u1 = sx[row[i+1]*4+j];
        uint2 u2 = sx[row[i+2]*4+j], u3 = sx[row[i+3]*4+j];
        uint2 u4 = sx[row[i+4]*4+j], u5 = sx[row[i+5]*4+j];
        uint2 u6 = sx[row[i+6]*4+j], u7 = sx[row[i+7]*4+j];
        acc_h4(acc, u0); acc_h4(acc, u1); acc_h4(acc, u2); acc_h4(acc, u3);
        acc_h4(acc, u4); acc_h4(acc, u5); acc_h4(acc, u6); acc_h4(acc, u7);
    }
    for (; i < end; i++) acc_h4(acc, sx[row[i]*4+j]);
    float d = g_dis[n];
    acc.x *= d; acc.y *= d; acc.z *= d; acc.w *= d;
    g_a16[n * 4 + j] = acc;
}

// ---- gemm: h = relu(a16@W1+b1); sx64 = (h@W2)*dis -> fp16 ----
// 8 lanes per 4-node group, f32x2 FMA, h packed fp16 in regs (16 regs), shfl pairs.
// __launch_bounds__(256,4): 64-reg cap -> 4 blocks/SM.
#define ASTR 20
__global__ void __launch_bounds__(256, 4) k_gemm(const float* __restrict__ W1,
                                                 const float* __restrict__ b1,
                                                 const float* __restrict__ W2) {
    __shared__ __align__(16) float sW1[FIN * H];      // 4KB
    __shared__ __align__(16) float sW2[H * H];        // 16KB
    __shared__ __align__(16) float sb1[H];
    __shared__ __align__(16) float sA[128 * ASTR];    // 10KB: 128 nodes' aggregates
    __shared__ float sdis[128];
    int tid = threadIdx.x;
    int lg = tid >> 3;                 // local group 0..31
    int j  = tid & 7;                  // lane-in-group
    int lane = tid & 31;
    int base_lane = lane & 24;         // first lane of this 8-lane group
    int grp = blockIdx.x * 32 + lg;    // global group (4 nodes each)
    int n0 = grp * 4;

    // vectorized preloads
    for (int k = tid; k < FIN * H / 4; k += 256) ((float4*)sW1)[k] = ((const float4*)W1)[k];
    for (int k = tid; k < H * H / 4; k += 256)   ((float4*)sW2)[k] = ((const float4*)W2)[k];
    if (tid < H) sb1[tid] = b1[tid];
    {
        int nb = blockIdx.x * 128;
        #pragma unroll
        for (int w = 0; w < 2; w++) {
            int idx = w * 256 + tid;           // 0..511
            int nn = idx >> 2, q = idx & 3;
            float4 v = make_float4(0.f, 0.f, 0.f, 0.f);
            if (nb + nn < N_NODES) v = g_a16[(nb + nn) * 4 + q];
            *(float4*)&sA[nn * ASTR + q * 4] = v;
        }
        if (tid < 128) sdis[tid] = (nb + tid < N_NODES) ? g_dis[nb + tid] : 0.0f;
    }
    __syncthreads();

    // phase 2: h = relu(a @ W1 + b1); f32x2 accumulators, then pack h to fp16 pairs.
    // h2u[m*4 + u*2 + (p>>1)] holds outputs (u*32 + 4j + p, ... + p+1), p in {0,2}.
    unsigned h2u[16];
    {
        unsigned long long acc2[16];
        float4 bq0 = *(const float4*)&sb1[j * 4];
        float4 bq1 = *(const float4*)&sb1[32 + j * 4];
        unsigned long long b0 = pk2(bq0.x, bq0.y), b1p = pk2(bq0.z, bq0.w);
        unsigned long long b2 = pk2(bq1.x, bq1.y), b3p = pk2(bq1.z, bq1.w);
        #pragma unroll
        for (int m = 0; m < 4; m++) {
            acc2[m*4+0] = b0; acc2[m*4+1] = b1p; acc2[m*4+2] = b2; acc2[m*4+3] = b3p;
        }
        #pragma unroll 4
        for (int k = 0; k < FIN; k++) {
            ulonglong2 wa = *(const ulonglong2*)&sW1[k * H + j * 4];
            ulonglong2 wb = *(const ulonglong2*)&sW1[k * H + 32 + j * 4];
            #pragma unroll
            for (int m = 0; m < 4; m++) {
                float av = sA[(lg * 4 + m) * ASTR + k];
                unsigned long long ap = pk2(av, av);
                fmax2(acc2[m*4+0], ap, wa.x);
                fmax2(acc2[m*4+1], ap, wa.y);
                fmax2(acc2[m*4+2], ap, wb.x);
                fmax2(acc2[m*4+3], ap, wb.y);
            }
        }
        #pragma unroll
        for (int q = 0; q < 16; q++) {
            float2 f = upk2(acc2[q]);
            __half2 hh = __floats2half2_rn(fmaxf(f.x, 0.0f), fmaxf(f.y, 0.0f));
            h2u[q] = *(unsigned*)&hh;
        }
    }

    // phase 3: k in pairs; one shfl'd half2 -> two k-steps; f32x2 accumulators
    unsigned long long acc3[16];
    #pragma unroll
    for (int q = 0; q < 16; q++) acc3[q] = 0ULL;
    #pragma unroll 4
    for (int kk = 0; kk < H; kk += 2) {
        int owner = (kk >> 2) & 7;                       // quad owner lane-in-group
        int h2idx = ((kk >> 5) << 1) | ((kk >> 1) & 1);  // half2 index at owner
        ulonglong2 wa0 = *(const ulonglong2*)&sW2[kk * H + j * 4];
        ulonglong2 wb0 = *(const ulonglong2*)&sW2[kk * H + 32 + j * 4];
        ulonglong2 wa1 = *(const ulonglong2*)&sW2[(kk + 1) * H + j * 4];
        ulonglong2 wb1 = *(const ulonglong2*)&sW2[(kk + 1) * H + 32 + j * 4];
        #pragma unroll
        for (int m = 0; m < 4; m++) {
            unsigned hv2 = __shfl_sync(0xffffffffu, h2u[m*4 + h2idx], base_lane + owner);
            float2 hf = __half22float2(*(__half2*)&hv2);
            unsigned long long hp0 = pk2(hf.x, hf.x);
            unsigned long long hp1 = pk2(hf.y, hf.y);
            fmax2(acc3[m*4+0], hp0, wa0.x);
            fmax2(acc3[m*4+1], hp0, wa0.y);
            fmax2(acc3[m*4+2], hp0, wb0.x);
            fmax2(acc3[m*4+3], hp0, wb0.y);
            fmax2(acc3[m*4+0], hp1, wa1.x);
            fmax2(acc3[m*4+1], hp1, wa1.y);
            fmax2(acc3[m*4+2], hp1, wb1.x);
            fmax2(acc3[m*4+3], hp1, wb1.y);
        }
    }
    // scale + fp16 pack + store (guarded; all shfl/compute above is warp-uniform)
    if (grp < NGRP) {
        #pragma unroll
        for (int m = 0; m < 4; m++) {
            int n = n0 + m;
            float d = sdis[lg * 4 + m];
            float2 f0 = upk2(acc3[m*4+0]), f1 = upk2(acc3[m*4+1]);
            float2 f2 = upk2(acc3[m*4+2]), f3 = upk2(acc3[m*4+3]);
            __half2 p0 = __floats2half2_rn(f0.x*d, f0.y*d);
            __half2 p1 = __floats2half2_rn(f1.x*d, f1.y*d);
            __half2 p2 = __floats2half2_rn(f2.x*d, f2.y*d);
            __half2 p3 = __floats2half2_rn(f3.x*d, f3.y*d);
            uint2* row = (uint2*)&g_sx64h[n * 32];
            uint2 u0, u1;
            u0.x = *(unsigned*)&p0; u0.y = *(unsigned*)&p1;
            u1.x = *(unsigned*)&p2; u1.y = *(unsigned*)&p3;
            row[j]     = u0;
            row[8 + j] = u1;
        }
    }
}

// ---------------- agg2 (64-wide fp16 gather, unroll 8) + final scorer ----------------
__global__ void __launch_bounds__(128) k_agg2_fin(const float* __restrict__ b2,
                                                  const float* __restrict__ Wf,
                                                  const float* __restrict__ bf,
                                                  float* __restrict__ out) {
    int tid = blockIdx.x * blockDim.x + threadIdx.x;   // 16 threads per node
    int n = tid >> 4, j = tid & 15;
    if (n >= N_NODES) return;
    const uint2* sx = (const uint2*)g_sx64h;           // 16 uint2 per 128B row
    const int* row = &g_csr[n * CAP];

    float4 acc = make_float4(0.f, 0.f, 0.f, 0.f);
    acc_h4(acc, sx[n * 16 + j]);                       // self-loop
    int end = g_deg[n]; if (end > CAP) end = CAP;
    int i = 0;
    for (; i + 8 <= end; i += 8) {
        uint2 u0 = sx[row[i+0]*16+j], u1 = sx[row[i+1]*16+j];
        uint2 u2 = sx[row[i+2]*16+j], u3 = sx[row[i+3]*16+j];
        uint2 u4 = sx[row[i+4]*16+j], u5 = sx[row[i+5]*16+j];
        uint2 u6 = sx[row[i+6]*16+j], u7 = sx[row[i+7]*16+j];
        acc_h4(acc, u0); acc_h4(acc, u1); acc_h4(acc, u2); acc_h4(acc, u3);
        acc_h4(acc, u4); acc_h4(acc, u5); acc_h4(acc, u6); acc_h4(acc, u7);
    }
    for (; i < end; i++) acc_h4(acc, sx[row[i]*16+j]);

    float d = g_dis[n];
    float4 b = ((const float4*)b2)[j];
    float4 w = ((const float4*)Wf)[j];
    float s = fmaxf(fmaf(acc.x, d, b.x), 0.0f) * w.x
            + fmaxf(fmaf(acc.y, d, b.y), 0.0f) * w.y
            + fmaxf(fmaf(acc.z, d, b.z), 0.0f) * w.z
            + fmaxf(fmaf(acc.w, d, b.w), 0.0f) * w.w;
    #pragma unroll
    for (int off = 8; off > 0; off >>= 1) s += __shfl_down_sync(0xffffffffu, s, off, 16);
    if (j == 0) out[n] = 1.0f / (1.0f + expf(-(s + bf[0])));
}

// ---------------- launch ----------------
extern "C" void kernel_launch(void* const* d_in, const int* in_sizes, int n_in,
                              void* d_out, int out_size) {
    int iX = 0, iEi = 1, iW1 = 2, iW2 = 4, iBf = 7;
    int p64[3] = {3, 5, 6}; int n64 = 0;
    for (int i = 0; i < n_in; i++) {
        int s = in_sizes[i];
        if (s == 2 * N_EDGES)        iEi = i;
        else if (s == N_NODES * FIN) iX = i;
        else if (s == FIN * H)       iW1 = i;
        else if (s == H * H)         iW2 = i;
        else if (s == 1)             iBf = i;
        else if (s == H && n64 < 3)  p64[n64++] = i;
    }
    int iB1, iB2, iWf;
    if (n64 == 3 && p64[0] > iW2) { iWf = p64[0]; iB1 = p64[1]; iB2 = p64[2]; }
    else                          { iB1 = p64[0]; iB2 = p64[1]; iWf = p64[2]; }

    const float* x  = (const float*)d_in[iX];
    const void*  ei = d_in[iEi];
    const float* W1 = (const float*)d_in[iW1];
    const float* b1 = (const float*)d_in[iB1];
    const float* W2 = (const float*)d_in[iW2];
    const float* b2 = (const float*)d_in[iB2];
    const float* Wf = (const float*)d_in[iWf];
    const float* bf = (const float*)d_in[iBf];
    float* out = (float*)d_out;

    // zero degree via captured memset node (graph-legal, no alloc)
    void* p_deg = nullptr;
    cudaGetSymbolAddress(&p_deg, g_deg);
    cudaMemsetAsync(p_deg, 0, N_NODES * sizeof(int));

    k_scatter <<<(N_EDGES / 8 + 255) / 256, 256>>>(ei);
    k_prep    <<<(N_NODES * 4 + 255) / 256, 256>>>(x);
    k_agg1    <<<(N_NODES * 4 + 255) / 256, 256>>>();
    k_gemm    <<<(NGRP + 31) / 32, 256>>>(W1, b1, W2);
    k_agg2_fin<<<(N_NODES * 16 + 127) / 128, 128>>>(b2, Wf, bf, out);
}